// round 11
// baseline (speedup 1.0000x reference)
#include <cuda_runtime.h>
#include <cuda_bf16.h>

#define PI_F 3.14159265358979323846f

// ---------------------------------------------------------------------------
// Globals (static device allocations are legal; runtime allocs are not)
// ---------------------------------------------------------------------------
// State S[b][x][y][f]: 512*128*128*2 complex64 = 134 MB
__device__ float2 g_S[16777216];
// Partial probabilities P2[b][x][ya*2+f] (yc already summed): 512*128*64 floats
__device__ float  g_P2[4194304];
// Precomputed mux unitaries: (cr, ax*sn, ay*sn, az*sn) per (layer, cond, xa, ya)
//   [0,16384):   mux0  idx = x*128 + y
//   [16384,32768): mux1 idx = ((cx*2+cy)*64 + xa)*64 + ya
//   [32768,36864): mux2 idx = ((cx*2+cy)*32 + xa)*32 + ya
__device__ float4 g_U[36864];

__device__ __forceinline__ float2 cmulf(float2 a, float2 b) {
    return make_float2(a.x * b.x - a.y * b.y, a.x * b.y + a.y * b.x);
}

// ---------------------------------------------------------------------------
// CTA-cooperative batched Stockham FFT (mixed radix 4/2), 256 threads.
// smem holds 16 physical lines of 128 complexes, padded stride 129 float2.
// For transform length L < 128 each line holds 128/L independent contiguous
// segments (exactly the per-condition-bit sub-transforms after pooling).
// Self-sorting; input in A, output ends in A; ortho scaling 1/sqrt(L).
// tw[k] = exp(-2*pi*i*k/128).
// ---------------------------------------------------------------------------
__device__ void cta_fft(float2* A, float2* B, const float2* tw, int lg2L, bool inverse)
{
    const int tid = threadIdx.x;
    const int L = 1 << lg2L;
    const int lg2nL = 11 - lg2L;           // log2(#logical lines) = log2(16*128/L)
    const int nLmask = (1 << lg2nL) - 1;
    const int step = 7 - lg2L;             // twiddle exponent scale 128/L
    const float scale = rsqrtf((float)L);
    const int off = L >> 2;                // s*m invariant (s*n == L)
    int n = L, s = 1;
    bool inA = true;
    while ((n & 3) == 0) {
        float2* src = inA ? A : B;
        const bool last = (n == 4);        // only hit for L=64 (in-place safe: same slots per item)
        float2* dst = last ? A : (inA ? B : A);
        const int sm1 = s - 1;
        #pragma unroll 2
        for (int w = tid; w < 512; w += 256) {
            int l = w & nLmask;
            int u = w >> lg2nL;            // u = q + s*p,  u in [0, L/4)
            int q = u & sm1;
            int base = (l & 15) * 129 + ((l >> 4) << lg2L);
            int i0 = base + u;
            float2 a0 = src[i0];
            float2 a1 = src[i0 + off];
            float2 a2 = src[i0 + 2 * off];
            float2 a3 = src[i0 + 3 * off];
            float2 t0 = make_float2(a0.x + a2.x, a0.y + a2.y);
            float2 t1 = make_float2(a0.x - a2.x, a0.y - a2.y);
            float2 t2 = make_float2(a1.x + a3.x, a1.y + a3.y);
            float2 t3 = make_float2(a1.x - a3.x, a1.y - a3.y);
            // forward: -i*(b-d); inverse: +i*(b-d)
            float2 jt = inverse ? make_float2(-t3.y, t3.x) : make_float2(t3.y, -t3.x);
            float2 y0 = make_float2(t0.x + t2.x, t0.y + t2.y);
            float2 y2 = make_float2(t0.x - t2.x, t0.y - t2.y);
            float2 y1 = make_float2(t1.x + jt.x, t1.y + jt.y);
            float2 y3 = make_float2(t1.x - jt.x, t1.y - jt.y);
            int e = (u - q) << step;       // p*s*(128/L) -> w1p = e^{-2pi i p/n}
            float2 w1 = tw[e], w2 = tw[2 * e], w3 = tw[3 * e];
            if (inverse) { w1.y = -w1.y; w2.y = -w2.y; w3.y = -w3.y; }
            float2 o1 = cmulf(y1, w1);
            float2 o2 = cmulf(y2, w2);
            float2 o3 = cmulf(y3, w3);
            if (last) {
                y0.x *= scale; y0.y *= scale;
                o1.x *= scale; o1.y *= scale;
                o2.x *= scale; o2.y *= scale;
                o3.x *= scale; o3.y *= scale;
            }
            int d0 = base + ((u - q) << 2) + q;  // q + 4*s*p
            dst[d0]         = y0;
            dst[d0 + s]     = o1;
            dst[d0 + 2 * s] = o2;
            dst[d0 + 3 * s] = o3;
        }
        __syncthreads();
        if (!last) inA = !inA;
        n >>= 2; s <<= 2;
    }
    if (n == 2) {
        // final radix-2 stage (p=0, twiddle=1); per-item read/write same slots -> in-place safe
        float2* src = inA ? A : B;
        #pragma unroll 4
        for (int w = tid; w < 1024; w += 256) {
            int l = w & nLmask;
            int u = w >> lg2nL;            // u in [0, L/2)
            int base = (l & 15) * 129 + ((l >> 4) << lg2L);
            float2 a = src[base + u];
            float2 b = src[base + u + s];
            A[base + u]     = make_float2((a.x + b.x) * scale, (a.y + b.y) * scale);
            A[base + u + s] = make_float2((a.x - b.x) * scale, (a.y - b.y) * scale);
        }
        __syncthreads();
    }
}

// exp(-i a.sigma) on the feature pair, from precomputed q = (cr, ax*sn, ay*sn, az*sn)
__device__ __forceinline__ void mux_apply(float4 q, float2& p0, float2& p1)
{
    float cr = q.x, sx = q.y, sy = q.z, sz = q.w;
    float2 n0 = make_float2(cr * p0.x + sz * p0.y - sy * p1.x + sx * p1.y,
                            cr * p0.y - sz * p0.x - sy * p1.y - sx * p1.x);
    float2 n1 = make_float2(sy * p0.x + sx * p0.y + cr * p1.x - sz * p1.y,
                            sy * p0.y - sx * p0.x + cr * p1.y + sz * p1.x);
    p0 = n0; p1 = n1;
}

#define DECL_SMEM                                                             \
    __shared__ float2 A[16 * 129];                                            \
    __shared__ float2 Bs[16 * 129];                                           \
    __shared__ float2 tw[128];                                                \
    const int tid = threadIdx.x;                                              \
    if (tid < 128) {                                                          \
        float sn, cs;                                                         \
        __sincosf(-2.0f * PI_F * (float)tid * (1.0f / 128.0f), &sn, &cs);     \
        tw[tid] = make_float2(cs, sn);                                        \
    }

// ---- K0: precompute the 36864 mux unitaries --------------------------------
__global__ void __launch_bounds__(256) k0_prep(const float* __restrict__ mux0,
                                               const float* __restrict__ mux1,
                                               const float* __restrict__ mux2)
{
    int i = blockIdx.x * 256 + threadIdx.x;
    if (i >= 36864) return;
    const float* src;
    if (i < 16384)      src = mux0 + (size_t)i * 3;
    else if (i < 32768) src = mux1 + (size_t)(i - 16384) * 3;
    else                src = mux2 + (size_t)(i - 32768) * 3;
    float ax = src[0], ay = src[1], az = src[2];
    float r = sqrtf(ax * ax + ay * ay + az * az + 1e-20f);
    float sr, cr;
    sincosf(r, &sr, &cr);
    float sn = sr / r;
    g_U[i] = make_float4(cr, ax * sn, ay * sn, az * sn);
}

// ---- K1: FRQI encode + FFTy(128). Row pass: 8 (b,x) rows per CTA -----------
__global__ void __launch_bounds__(256) k1_row(const float* __restrict__ images)
{
    DECL_SMEM
    int bi = blockIdx.x >> 4;
    int x0 = (blockIdx.x & 15) << 3;
    const float* img = images + (size_t)(bi * 128 + x0) * 128;
    for (int e = tid; e < 1024; e += 256) {
        int r = e >> 7, y = e & 127;
        float v = img[r * 128 + y];
        float sn, cs;
        __sincosf(0.5f * PI_F * v, &sn, &cs);
        A[(2 * r) * 129 + y]     = make_float2(cs * (1.0f / 128.0f), 0.0f);
        A[(2 * r + 1) * 129 + y] = make_float2(sn * (1.0f / 128.0f), 0.0f);
    }
    __syncthreads();
    cta_fft(A, Bs, tw, 7, false);
    float2* Sg = g_S + (size_t)(bi * 128 + x0) * 256;
    for (int e = tid; e < 2048; e += 256) {
        int r = e >> 8, t = e & 255;
        Sg[e] = A[(2 * r + (t & 1)) * 129 + (t >> 1)];
    }
}

// ---- K2: FFTx128 . mux0 . IFFTx128 . FFTx64. Col pass: 8 y per CTA ---------
__global__ void __launch_bounds__(256) k2_col()
{
    DECL_SMEM
    int bi = blockIdx.x >> 4;
    int y0 = (blockIdx.x & 15) << 3;
    float2* Sg = g_S + (size_t)bi * 32768 + y0 * 2;
    for (int e = tid; e < 2048; e += 256) {
        int x = e >> 4, c = e & 15;            // c = yl*2 + f
        A[c * 129 + x] = Sg[x * 256 + c];
    }
    __syncthreads();
    cta_fft(A, Bs, tw, 7, false);
    for (int w = tid; w < 1024; w += 256) {
        int yl = w >> 7, x = w & 127;
        int y = y0 + yl;
        float4 q = g_U[x * 128 + y];
        float2 p0 = A[(2 * yl) * 129 + x];
        float2 p1 = A[(2 * yl + 1) * 129 + x];
        mux_apply(q, p0, p1);
        A[(2 * yl) * 129 + x]     = p0;
        A[(2 * yl + 1) * 129 + x] = p1;
    }
    __syncthreads();
    cta_fft(A, Bs, tw, 7, true);
    cta_fft(A, Bs, tw, 6, false);
    for (int e = tid; e < 2048; e += 256) {
        int x = e >> 4, c = e & 15;
        Sg[x * 256 + c] = A[c * 129 + x];
    }
}

// ---- K3: IFFTy128 . FFTy64 . mux1 . IFFTy64 . FFTy32. Row pass -------------
__global__ void __launch_bounds__(256) k3_row()
{
    DECL_SMEM
    int bi = blockIdx.x >> 4;
    int x0 = (blockIdx.x & 15) << 3;
    float2* Sg = g_S + (size_t)(bi * 128 + x0) * 256;
    for (int e = tid; e < 2048; e += 256) {
        int r = e >> 8, t = e & 255;
        A[(2 * r + (t & 1)) * 129 + (t >> 1)] = Sg[e];
    }
    __syncthreads();
    cta_fft(A, Bs, tw, 7, true);
    cta_fft(A, Bs, tw, 6, false);
    for (int w = tid; w < 1024; w += 256) {
        int r = w >> 7, y = w & 127;
        int x = x0 + r;
        int cx = x >> 6, xa = x & 63;
        int cy = y >> 6, ya = y & 63;
        float4 q = g_U[16384 + ((cx * 2 + cy) * 64 + xa) * 64 + ya];
        float2 p0 = A[(2 * r) * 129 + y];
        float2 p1 = A[(2 * r + 1) * 129 + y];
        mux_apply(q, p0, p1);
        A[(2 * r) * 129 + y]     = p0;
        A[(2 * r + 1) * 129 + y] = p1;
    }
    __syncthreads();
    cta_fft(A, Bs, tw, 6, true);
    cta_fft(A, Bs, tw, 5, false);
    for (int e = tid; e < 2048; e += 256) {
        int r = e >> 8, t = e & 255;
        Sg[e] = A[(2 * r + (t & 1)) * 129 + (t >> 1)];
    }
}

// ---- K4: IFFTx64 . FFTx32 . mux2 . IFFTx32. Col pass -----------------------
__global__ void __launch_bounds__(256) k4_col()
{
    DECL_SMEM
    int bi = blockIdx.x >> 4;
    int y0 = (blockIdx.x & 15) << 3;
    float2* Sg = g_S + (size_t)bi * 32768 + y0 * 2;
    for (int e = tid; e < 2048; e += 256) {
        int x = e >> 4, c = e & 15;
        A[c * 129 + x] = Sg[x * 256 + c];
    }
    __syncthreads();
    cta_fft(A, Bs, tw, 6, true);
    cta_fft(A, Bs, tw, 5, false);
    for (int w = tid; w < 1024; w += 256) {
        int yl = w >> 7, x = w & 127;
        int y = y0 + yl;
        int cx = (x >> 5) & 1, xa = x & 31;
        int cy = (y >> 5) & 1, ya = y & 31;
        float4 q = g_U[32768 + ((cx * 2 + cy) * 32 + xa) * 32 + ya];
        float2 p0 = A[(2 * yl) * 129 + x];
        float2 p1 = A[(2 * yl + 1) * 129 + x];
        mux_apply(q, p0, p1);
        A[(2 * yl) * 129 + x]     = p0;
        A[(2 * yl + 1) * 129 + x] = p1;
    }
    __syncthreads();
    cta_fft(A, Bs, tw, 5, true);
    for (int e = tid; e < 2048; e += 256) {
        int x = e >> 4, c = e & 15;
        Sg[x * 256 + c] = A[c * 129 + x];
    }
}

// ---- K5: IFFTy32 + measure (sum over yc). Row pass -------------------------
__global__ void __launch_bounds__(256) k5_row()
{
    DECL_SMEM
    int bi = blockIdx.x >> 4;
    int x0 = (blockIdx.x & 15) << 3;
    float2* Sg = g_S + (size_t)(bi * 128 + x0) * 256;
    for (int e = tid; e < 2048; e += 256) {
        int r = e >> 8, t = e & 255;
        A[(2 * r + (t & 1)) * 129 + (t >> 1)] = Sg[e];
    }
    __syncthreads();
    cta_fft(A, Bs, tw, 5, true);
    for (int w = tid; w < 512; w += 256) {
        int r = w >> 6, f = (w >> 5) & 1, ya = w & 31;
        const float2* line = A + (2 * r + f) * 129;
        float sum = 0.0f;
        #pragma unroll
        for (int g = 0; g < 4; g++) {
            float2 v = line[g * 32 + ya];
            sum += v.x * v.x + v.y * v.y;
        }
        int x = x0 + r;
        g_P2[(size_t)bi * 8192 + x * 64 + ya * 2 + f] = sum;
    }
}

// ---- K6: reduce over xc + [1,2048]x[2048,10] GEMM + bias -------------------
__global__ void __launch_bounds__(256) k6_gemm(const float* __restrict__ W,
                                               const float* __restrict__ bias,
                                               float* __restrict__ out)
{
    __shared__ float acc[2048];
    __shared__ float red[8][10];
    const int tid = threadIdx.x;
    const int bi = blockIdx.x;
    const float* P = g_P2 + (size_t)bi * 8192;   // [x][ya*2+f] = [128][64]
    for (int j = tid; j < 2048; j += 256) {
        int xa = j >> 6, t = j & 63;
        acc[j] = P[xa * 64 + t] + P[(32 + xa) * 64 + t]
               + P[(64 + xa) * 64 + t] + P[(96 + xa) * 64 + t];
    }
    __syncthreads();
    float part[10];
    #pragma unroll
    for (int c = 0; c < 10; c++) part[c] = 0.0f;
    for (int j = tid; j < 2048; j += 256) {
        float v = acc[j];
        #pragma unroll
        for (int c = 0; c < 10; c++) part[c] += v * W[c * 2048 + j];
    }
    #pragma unroll
    for (int o = 16; o > 0; o >>= 1) {
        #pragma unroll
        for (int c = 0; c < 10; c++)
            part[c] += __shfl_xor_sync(0xffffffffu, part[c], o);
    }
    if ((tid & 31) == 0) {
        int wi = tid >> 5;
        #pragma unroll
        for (int c = 0; c < 10; c++) red[wi][c] = part[c];
    }
    __syncthreads();
    if (tid < 10) {
        float s = bias[tid];
        #pragma unroll
        for (int wi = 0; wi < 8; wi++) s += red[wi][tid];
        out[bi * 10 + tid] = s;
    }
}

// ---------------------------------------------------------------------------
extern "C" void kernel_launch(void* const* d_in, const int* in_sizes, int n_in,
                              void* d_out, int out_size)
{
    const float* images = (const float*)d_in[0];
    const float* mux0   = (const float*)d_in[1];
    const float* mux1   = (const float*)d_in[2];
    const float* mux2   = (const float*)d_in[3];
    const float* W      = (const float*)d_in[4];
    const float* bias   = (const float*)d_in[5];
    float* out = (float*)d_out;

    k0_prep<<<144, 256>>>(mux0, mux1, mux2);
    k1_row<<<8192, 256>>>(images);
    k2_col<<<8192, 256>>>();
    k3_row<<<8192, 256>>>();
    k4_col<<<8192, 256>>>();
    k5_row<<<8192, 256>>>();
    k6_gemm<<<512, 256>>>(W, bias, out);
}

// round 12
// speedup vs baseline: 1.1308x; 1.1308x over previous
#include <cuda_runtime.h>
#include <cuda_bf16.h>

#define PI_F 3.14159265358979323846f
#define SQ2H 0.70710678118654752440f

// ---------------------------------------------------------------------------
// Static device scratch (runtime allocation is forbidden)
// ---------------------------------------------------------------------------
// State S[b][x][y][f]: 512*128*128*2 complex64 = 134 MB
__device__ float2 g_S[16777216];
// Partial probabilities P2[b][x][ya*2+f] (yc already summed): 512*128*64 floats
__device__ float  g_P2[4194304];
// Precomputed mux unitaries: (cr, ax*sn, ay*sn, az*sn)
//   [0,16384):     mux0 idx = x*128 + y
//   [16384,32768): mux1 idx = ((cx*2+cy)*64 + xa)*64 + ya
//   [32768,36864): mux2 idx = ((cx*2+cy)*32 + xa)*32 + ya
__device__ float4 g_U[36864];

__device__ __forceinline__ float2 cmulf(float2 a, float2 b) {
    return make_float2(a.x * b.x - a.y * b.y, a.x * b.y + a.y * b.x);
}
__device__ __forceinline__ float2 cadd(float2 a, float2 b) { return make_float2(a.x + b.x, a.y + b.y); }
__device__ __forceinline__ float2 csub(float2 a, float2 b) { return make_float2(a.x - b.x, a.y - b.y); }

template<bool INV>
__device__ __forceinline__ float2 mul_j(float2 t) {
    // forward: -i*t ; inverse: +i*t
    return INV ? make_float2(-t.y, t.x) : make_float2(t.y, -t.x);
}

template<bool INV>
__device__ __forceinline__ float2 twget(const float2* tw, int idx) {
    float2 w = tw[idx];
    if (INV) w.y = -w.y;
    return w;
}

// ---------------------------------------------------------------------------
// DFT-8 butterfly, fully in registers.
// ---------------------------------------------------------------------------
template<bool INV>
__device__ __forceinline__ void bfly8(const float2 a[8], float2 y[8])
{
    // even DFT4: a0,a2,a4,a6
    float2 t0 = cadd(a[0], a[4]), t1 = csub(a[0], a[4]);
    float2 t2 = cadd(a[2], a[6]), t3 = csub(a[2], a[6]);
    float2 jt3 = mul_j<INV>(t3);
    float2 E0 = cadd(t0, t2), E1 = cadd(t1, jt3), E2 = csub(t0, t2), E3 = csub(t1, jt3);
    // odd DFT4: a1,a3,a5,a7
    float2 s0 = cadd(a[1], a[5]), s1 = csub(a[1], a[5]);
    float2 s2 = cadd(a[3], a[7]), s3 = csub(a[3], a[7]);
    float2 js3 = mul_j<INV>(s3);
    float2 O0 = cadd(s0, s2), O1 = cadd(s1, js3), O2 = csub(s0, s2), O3 = csub(s1, js3);
    // multiply odd outputs by omega8^k
    float2 O1p, O2p, O3p;
    if (!INV) {
        O1p = make_float2(SQ2H * (O1.x + O1.y),  SQ2H * (O1.y - O1.x));  // * c(1-i)
        O2p = make_float2(O2.y, -O2.x);                                  // * -i
        O3p = make_float2(-SQ2H * (O3.x - O3.y), -SQ2H * (O3.x + O3.y)); // * -c(1+i)
    } else {
        O1p = make_float2(SQ2H * (O1.x - O1.y),  SQ2H * (O1.x + O1.y));  // * c(1+i)
        O2p = make_float2(-O2.y, O2.x);                                  // * +i
        O3p = make_float2(-SQ2H * (O3.x + O3.y), -SQ2H * (O3.y - O3.x)); // * -c(1-i)
    }
    y[0] = cadd(E0, O0);  y[4] = csub(E0, O0);
    y[1] = cadd(E1, O1p); y[5] = csub(E1, O1p);
    y[2] = cadd(E2, O2p); y[6] = csub(E2, O2p);
    y[3] = cadd(E3, O3p); y[7] = csub(E3, O3p);
}

// ---------------------------------------------------------------------------
// One radix-8 Stockham stage over 2048 smem-resident elements (16 padded
// lines of 128 float2, pad stride 129; lengths L<128 are 128/L contiguous
// segments per line). Exactly 1 butterfly per thread. All indexing constexpr.
//   item u = q + S*p, q in [0,S), reads src[base+u+j*L/8],
//   twiddle w_k = omega_L^{S*p*k}, writes dst[base+q+8*S*p+k*S].
// ---------------------------------------------------------------------------
template<int LG2L, int S, bool INV, bool SCALE, bool NOTW>
__device__ __forceinline__ void stage8(const float2* __restrict__ src,
                                       float2* __restrict__ dst,
                                       const float2* tw, int tid)
{
    constexpr int L = 1 << LG2L;
    constexpr int LG2NL = 11 - LG2L;           // log2(#logical lines)
    constexpr int NLMASK = (1 << LG2NL) - 1;
    constexpr int STEP = 7 - LG2L;             // twiddle exponent scale 128/L
    constexpr int OFF = L / 8;
    const int l = tid & NLMASK;
    const int u = tid >> LG2NL;                // in [0, L/8)
    const int q = u & (S - 1);
    const int ps = u - q;                      // S*p
    const int base = (l & 15) * 129 + ((l >> 4) << LG2L);

    float2 a[8], y[8];
    #pragma unroll
    for (int j = 0; j < 8; j++) a[j] = src[base + u + j * OFF];
    bfly8<INV>(a, y);
    if (!NOTW) {
        const int e = ps << STEP;
        #pragma unroll
        for (int k = 1; k < 8; k++) y[k] = cmulf(y[k], twget<INV>(tw, k * e));
    }
    if (SCALE) {
        constexpr float sc = 0.125f;           // only used as final stage of L=64
        #pragma unroll
        for (int k = 0; k < 8; k++) { y[k].x *= sc; y[k].y *= sc; }
    }
    const int d0 = base + q + 8 * ps;
    #pragma unroll
    for (int k = 0; k < 8; k++) dst[d0 + k * S] = y[k];
}

// Final radix-2 stage for L=128 (s=64, p==0 -> trivial twiddle), in-place safe.
__device__ __forceinline__ void stage2_128(float2* __restrict__ A, int tid)
{
    constexpr float sc = 0.08838834764831845f; // 1/sqrt(128)
    #pragma unroll
    for (int w = tid; w < 1024; w += 256) {
        int l = w & 15;
        int u = w >> 4;                        // [0,64)
        int base = l * 129;
        float2 a = A[base + u], b = A[base + u + 64];
        A[base + u]      = make_float2((a.x + b.x) * sc, (a.y + b.y) * sc);
        A[base + u + 64] = make_float2((a.x - b.x) * sc, (a.y - b.y) * sc);
    }
}

// Final radix-4 stage for L=32 (s=8, n=4, p==0 -> trivial twiddles), B -> A.
template<bool INV>
__device__ __forceinline__ void stage4_32(float2* __restrict__ A,
                                          const float2* __restrict__ B, int tid)
{
    constexpr float sc = 0.17677669529663687f; // 1/sqrt(32)
    #pragma unroll
    for (int w = tid; w < 512; w += 256) {
        int l = w & 63;
        int u = w >> 6;                        // [0,8) == q
        int base = (l & 15) * 129 + ((l >> 4) << 5);
        float2 a0 = B[base + u], a1 = B[base + u + 8];
        float2 a2 = B[base + u + 16], a3 = B[base + u + 24];
        float2 t0 = cadd(a0, a2), t1 = csub(a0, a2);
        float2 t2 = cadd(a1, a3), t3 = csub(a1, a3);
        float2 jt = mul_j<INV>(t3);
        A[base + u]      = make_float2((t0.x + t2.x) * sc, (t0.y + t2.y) * sc);
        A[base + u + 8]  = make_float2((t1.x + jt.x) * sc, (t1.y + jt.y) * sc);
        A[base + u + 16] = make_float2((t0.x - t2.x) * sc, (t0.y - t2.y) * sc);
        A[base + u + 24] = make_float2((t1.x - jt.x) * sc, (t1.y - jt.y) * sc);
    }
}

// Composite transforms: input in A, output in A.
template<bool INV>
__device__ __forceinline__ void fft128(float2* A, float2* B, const float2* tw, int tid) {
    stage8<7, 1, INV, false, false>(A, B, tw, tid); __syncthreads();
    stage8<7, 8, INV, false, false>(B, A, tw, tid); __syncthreads();
    stage2_128(A, tid);                             __syncthreads();
}
template<bool INV>
__device__ __forceinline__ void fft64(float2* A, float2* B, const float2* tw, int tid) {
    stage8<6, 1, INV, false, false>(A, B, tw, tid); __syncthreads();
    stage8<6, 8, INV, true,  true >(B, A, tw, tid); __syncthreads(); // p==0: no twiddle
}
template<bool INV>
__device__ __forceinline__ void fft32(float2* A, float2* B, const float2* tw, int tid) {
    stage8<5, 1, INV, false, false>(A, B, tw, tid); __syncthreads();
    stage4_32<INV>(A, B, tid);                      __syncthreads();
}

// exp(-i a.sigma) on the feature pair, q = (cr, ax*sn, ay*sn, az*sn)
__device__ __forceinline__ void mux_apply(float4 q, float2& p0, float2& p1)
{
    float cr = q.x, sx = q.y, sy = q.z, sz = q.w;
    float2 n0 = make_float2(cr * p0.x + sz * p0.y - sy * p1.x + sx * p1.y,
                            cr * p0.y - sz * p0.x - sy * p1.y - sx * p1.x);
    float2 n1 = make_float2(sy * p0.x + sx * p0.y + cr * p1.x - sz * p1.y,
                            sy * p0.y - sx * p0.x + cr * p1.y + sz * p1.x);
    p0 = n0; p1 = n1;
}

#define DECL_SMEM                                                             \
    __shared__ float2 A[16 * 129];                                            \
    __shared__ float2 Bs[16 * 129];                                           \
    __shared__ float2 tw[128];                                                \
    const int tid = threadIdx.x;                                              \
    if (tid < 128) {                                                          \
        float sn, cs;                                                         \
        __sincosf(-2.0f * PI_F * (float)tid * (1.0f / 128.0f), &sn, &cs);     \
        tw[tid] = make_float2(cs, sn);                                        \
    }

// ---- K0: precompute the 36864 mux unitaries --------------------------------
__global__ void __launch_bounds__(256) k0_prep(const float* __restrict__ mux0,
                                               const float* __restrict__ mux1,
                                               const float* __restrict__ mux2)
{
    int i = blockIdx.x * 256 + threadIdx.x;
    if (i >= 36864) return;
    const float* src;
    if (i < 16384)      src = mux0 + (size_t)i * 3;
    else if (i < 32768) src = mux1 + (size_t)(i - 16384) * 3;
    else                src = mux2 + (size_t)(i - 32768) * 3;
    float ax = src[0], ay = src[1], az = src[2];
    float r = sqrtf(ax * ax + ay * ay + az * az + 1e-20f);
    float sr, cr;
    sincosf(r, &sr, &cr);
    float sn = sr / r;
    g_U[i] = make_float4(cr, ax * sn, ay * sn, az * sn);
}

// ---- K1: FRQI encode + FFTy(128). Row pass: 8 (b,x) rows per CTA -----------
__global__ void __launch_bounds__(256) k1_row(const float* __restrict__ images)
{
    DECL_SMEM
    int bi = blockIdx.x >> 4;
    int x0 = (blockIdx.x & 15) << 3;
    const float* img = images + (size_t)(bi * 128 + x0) * 128;
    for (int e = tid; e < 1024; e += 256) {
        int r = e >> 7, y = e & 127;
        float v = img[r * 128 + y];
        float sn, cs;
        __sincosf(0.5f * PI_F * v, &sn, &cs);
        A[(2 * r) * 129 + y]     = make_float2(cs * (1.0f / 128.0f), 0.0f);
        A[(2 * r + 1) * 129 + y] = make_float2(sn * (1.0f / 128.0f), 0.0f);
    }
    __syncthreads();
    fft128<false>(A, Bs, tw, tid);
    float2* Sg = g_S + (size_t)(bi * 128 + x0) * 256;
    for (int e = tid; e < 2048; e += 256) {
        int r = e >> 8, t = e & 255;
        Sg[e] = A[(2 * r + (t & 1)) * 129 + (t >> 1)];
    }
}

// ---- K2: FFTx128 . mux0 . IFFTx128 . FFTx64. Col pass: 8 y per CTA ---------
__global__ void __launch_bounds__(256) k2_col()
{
    DECL_SMEM
    int bi = blockIdx.x >> 4;
    int y0 = (blockIdx.x & 15) << 3;
    float2* Sg = g_S + (size_t)bi * 32768 + y0 * 2;
    for (int e = tid; e < 2048; e += 256) {
        int x = e >> 4, c = e & 15;            // c = yl*2 + f
        A[c * 129 + x] = Sg[x * 256 + c];
    }
    __syncthreads();
    fft128<false>(A, Bs, tw, tid);
    for (int w = tid; w < 1024; w += 256) {
        int yl = w >> 7, x = w & 127;
        int y = y0 + yl;
        float4 q = g_U[x * 128 + y];
        float2 p0 = A[(2 * yl) * 129 + x];
        float2 p1 = A[(2 * yl + 1) * 129 + x];
        mux_apply(q, p0, p1);
        A[(2 * yl) * 129 + x]     = p0;
        A[(2 * yl + 1) * 129 + x] = p1;
    }
    __syncthreads();
    fft128<true>(A, Bs, tw, tid);
    fft64<false>(A, Bs, tw, tid);
    for (int e = tid; e < 2048; e += 256) {
        int x = e >> 4, c = e & 15;
        Sg[x * 256 + c] = A[c * 129 + x];
    }
}

// ---- K3: IFFTy128 . FFTy64 . mux1 . IFFTy64 . FFTy32. Row pass -------------
__global__ void __launch_bounds__(256) k3_row()
{
    DECL_SMEM
    int bi = blockIdx.x >> 4;
    int x0 = (blockIdx.x & 15) << 3;
    float2* Sg = g_S + (size_t)(bi * 128 + x0) * 256;
    for (int e = tid; e < 2048; e += 256) {
        int r = e >> 8, t = e & 255;
        A[(2 * r + (t & 1)) * 129 + (t >> 1)] = Sg[e];
    }
    __syncthreads();
    fft128<true>(A, Bs, tw, tid);
    fft64<false>(A, Bs, tw, tid);
    for (int w = tid; w < 1024; w += 256) {
        int r = w >> 7, y = w & 127;
        int x = x0 + r;
        int cx = x >> 6, xa = x & 63;
        int cy = y >> 6, ya = y & 63;
        float4 q = g_U[16384 + ((cx * 2 + cy) * 64 + xa) * 64 + ya];
        float2 p0 = A[(2 * r) * 129 + y];
        float2 p1 = A[(2 * r + 1) * 129 + y];
        mux_apply(q, p0, p1);
        A[(2 * r) * 129 + y]     = p0;
        A[(2 * r + 1) * 129 + y] = p1;
    }
    __syncthreads();
    fft64<true>(A, Bs, tw, tid);
    fft32<false>(A, Bs, tw, tid);
    for (int e = tid; e < 2048; e += 256) {
        int r = e >> 8, t = e & 255;
        Sg[e] = A[(2 * r + (t & 1)) * 129 + (t >> 1)];
    }
}

// ---- K4: IFFTx64 . FFTx32 . mux2 . IFFTx32. Col pass -----------------------
__global__ void __launch_bounds__(256) k4_col()
{
    DECL_SMEM
    int bi = blockIdx.x >> 4;
    int y0 = (blockIdx.x & 15) << 3;
    float2* Sg = g_S + (size_t)bi * 32768 + y0 * 2;
    for (int e = tid; e < 2048; e += 256) {
        int x = e >> 4, c = e & 15;
        A[c * 129 + x] = Sg[x * 256 + c];
    }
    __syncthreads();
    fft64<true>(A, Bs, tw, tid);
    fft32<false>(A, Bs, tw, tid);
    for (int w = tid; w < 1024; w += 256) {
        int yl = w >> 7, x = w & 127;
        int y = y0 + yl;
        int cx = (x >> 5) & 1, xa = x & 31;
        int cy = (y >> 5) & 1, ya = y & 31;
        float4 q = g_U[32768 + ((cx * 2 + cy) * 32 + xa) * 32 + ya];
        float2 p0 = A[(2 * yl) * 129 + x];
        float2 p1 = A[(2 * yl + 1) * 129 + x];
        mux_apply(q, p0, p1);
        A[(2 * yl) * 129 + x]     = p0;
        A[(2 * yl + 1) * 129 + x] = p1;
    }
    __syncthreads();
    fft32<true>(A, Bs, tw, tid);
    for (int e = tid; e < 2048; e += 256) {
        int x = e >> 4, c = e & 15;
        Sg[x * 256 + c] = A[c * 129 + x];
    }
}

// ---- K5: IFFTy32 + measure (sum over yc). Row pass -------------------------
__global__ void __launch_bounds__(256) k5_row()
{
    DECL_SMEM
    int bi = blockIdx.x >> 4;
    int x0 = (blockIdx.x & 15) << 3;
    float2* Sg = g_S + (size_t)(bi * 128 + x0) * 256;
    for (int e = tid; e < 2048; e += 256) {
        int r = e >> 8, t = e & 255;
        A[(2 * r + (t & 1)) * 129 + (t >> 1)] = Sg[e];
    }
    __syncthreads();
    fft32<true>(A, Bs, tw, tid);
    for (int w = tid; w < 512; w += 256) {
        int r = w >> 6, f = (w >> 5) & 1, ya = w & 31;
        const float2* line = A + (2 * r + f) * 129;
        float sum = 0.0f;
        #pragma unroll
        for (int g = 0; g < 4; g++) {
            float2 v = line[g * 32 + ya];
            sum += v.x * v.x + v.y * v.y;
        }
        int x = x0 + r;
        g_P2[(size_t)bi * 8192 + x * 64 + ya * 2 + f] = sum;
    }
}

// ---- K6: reduce over xc + [1,2048]x[2048,10] GEMM + bias -------------------
__global__ void __launch_bounds__(256) k6_gemm(const float* __restrict__ W,
                                               const float* __restrict__ bias,
                                               float* __restrict__ out)
{
    __shared__ float acc[2048];
    __shared__ float red[8][10];
    const int tid = threadIdx.x;
    const int bi = blockIdx.x;
    const float* P = g_P2 + (size_t)bi * 8192;   // [x][ya*2+f] = [128][64]
    for (int j = tid; j < 2048; j += 256) {
        int xa = j >> 6, t = j & 63;
        acc[j] = P[xa * 64 + t] + P[(32 + xa) * 64 + t]
               + P[(64 + xa) * 64 + t] + P[(96 + xa) * 64 + t];
    }
    __syncthreads();
    float part[10];
    #pragma unroll
    for (int c = 0; c < 10; c++) part[c] = 0.0f;
    for (int j = tid; j < 2048; j += 256) {
        float v = acc[j];
        #pragma unroll
        for (int c = 0; c < 10; c++) part[c] += v * W[c * 2048 + j];
    }
    #pragma unroll
    for (int o = 16; o > 0; o >>= 1) {
        #pragma unroll
        for (int c = 0; c < 10; c++)
            part[c] += __shfl_xor_sync(0xffffffffu, part[c], o);
    }
    if ((tid & 31) == 0) {
        int wi = tid >> 5;
        #pragma unroll
        for (int c = 0; c < 10; c++) red[wi][c] = part[c];
    }
    __syncthreads();
    if (tid < 10) {
        float s = bias[tid];
        #pragma unroll
        for (int wi = 0; wi < 8; wi++) s += red[wi][tid];
        out[bi * 10 + tid] = s;
    }
}

// ---------------------------------------------------------------------------
extern "C" void kernel_launch(void* const* d_in, const int* in_sizes, int n_in,
                              void* d_out, int out_size)
{
    const float* images = (const float*)d_in[0];
    const float* mux0   = (const float*)d_in[1];
    const float* mux1   = (const float*)d_in[2];
    const float* mux2   = (const float*)d_in[3];
    const float* W      = (const float*)d_in[4];
    const float* bias   = (const float*)d_in[5];
    float* out = (float*)d_out;

    k0_prep<<<144, 256>>>(mux0, mux1, mux2);
    k1_row<<<8192, 256>>>(images);
    k2_col<<<8192, 256>>>();
    k3_row<<<8192, 256>>>();
    k4_col<<<8192, 256>>>();
    k5_row<<<8192, 256>>>();
    k6_gemm<<<512, 256>>>(W, bias, out);
}